// round 9
// baseline (speedup 1.0000x reference)
#include <cuda_runtime.h>
#include <cuda_fp16.h>
#include <float.h>

// Problem-size upper bounds (from reference setup_inputs)
#define MAXN 50000
#define MAXE 800000
#define MAXET (MAXE + MAXN)   // + self loops

// ---------------- device scratch --------------------------------------------
__device__ float  g_hfeat[MAXN * 64];
__device__ __half g_hlin16[MAXN * 64];   // projected features, fp16 (agg input)
__device__ float  g_esrc [MAXN];
__device__ float  g_edst [MAXN];
__device__ float  g_ew   [MAXET];
__device__ int    g_hist [MAXN];
__device__ int    g_off  [MAXN + 1];
__device__ int    g_cursor[MAXN];
__device__ int    g_srcs [MAXET];

// ---------------- helpers ---------------------------------------------------
__device__ __forceinline__ float gat_warp_sum(float v) {
#pragma unroll
    for (int o = 16; o; o >>= 1) v += __shfl_xor_sync(0xffffffffu, v, o);
    return v;
}
__device__ __forceinline__ float gat_warp_max(float v) {
#pragma unroll
    for (int o = 16; o; o >>= 1) v = fmaxf(v, __shfl_xor_sync(0xffffffffu, v, o));
    return v;
}

// ---------------- edge sorting (counting sort by dst) -----------------------
__global__ void gat_zero_kernel(int n) {
    int i = blockIdx.x * blockDim.x + threadIdx.x;
    if (i < n) g_hist[i] = 0;
}

// edge_index is int32 [2, E] row-major: ei[i] = src, ei[E+i] = dst.
__global__ void gat_hist_kernel(const int* __restrict__ ei, int E, int n) {
    int i = blockIdx.x * blockDim.x + threadIdx.x;
    int total = E + n;
    if (i >= total) return;
    int d = (i < E) ? ei[E + i] : (i - E);
    if ((unsigned)d >= (unsigned)n) return;
    atomicAdd(&g_hist[d], 1);
}

__global__ void gat_scan_kernel(int n) {
    __shared__ int partial[1024];
    int t = threadIdx.x;
    int chunk = (n + 1023) / 1024;
    int begin = t * chunk;
    int endi  = min(begin + chunk, n);
    int sum = 0;
    for (int i = begin; i < endi; i++) sum += g_hist[i];
    partial[t] = sum;
    __syncthreads();
#pragma unroll
    for (int d = 1; d < 1024; d <<= 1) {
        int v = (t >= d) ? partial[t - d] : 0;
        __syncthreads();
        partial[t] += v;
        __syncthreads();
    }
    int run = (t == 0) ? 0 : partial[t - 1];
    for (int i = begin; i < endi; i++) {
        g_off[i]    = run;
        g_cursor[i] = run;
        run += g_hist[i];
    }
    if (t == 0) g_off[n] = partial[1023];
}

__global__ void gat_scatter_kernel(const int* __restrict__ ei, int E, int n) {
    int i = blockIdx.x * blockDim.x + threadIdx.x;
    int total = E + n;
    if (i >= total) return;
    int s, d;
    if (i < E) { s = ei[i]; d = ei[E + i]; }
    else       { s = d = i - E; }
    if ((unsigned)d >= (unsigned)n || (unsigned)s >= (unsigned)n) return;
    int pos = atomicAdd(&g_cursor[d], 1);
    g_srcs[pos] = s;
}

// ---------------- tiled GEMM: out = X @ W^T (+bias), optional e_src/e_dst ---
// Block = 256 threads, tile = ROWS x FOUT. W stored c-major with float4 XOR
// swizzle: (c, k4) at Ws[c*FIN + 4*(k4 ^ (c&7))] -> conflict-free both ways.
// SRCSEL: 0 = param X, 1 = g_hfeat.
// DSTSEL: 0 = fp32 g_hfeat, 1 = fp16 g_hlin16 (attention scores stay fp32).
template <int FIN, int FOUT, int ROWS, bool BIAS, bool COMPE, int SRCSEL, int DSTSEL>
__global__ void gat_gemm_kernel(const float* __restrict__ Xparam,
                                const float* __restrict__ W,
                                const float* __restrict__ bias,
                                const float* __restrict__ a_s,
                                const float* __restrict__ a_d,
                                int n) {
    const float* X = (SRCSEL == 0) ? Xparam : g_hfeat;

    constexpr int COLS = FOUT / 32;
    constexpr int RPT  = ROWS / 8;
    constexpr int QF   = FIN / 4;

    __shared__ float xs[ROWS * FIN];
    __shared__ float Ws[FOUT * FIN];

    int t  = threadIdx.x;
    int r0 = blockIdx.x * ROWS;

    {
        const float4* W4 = (const float4*)W;
        for (int idx = t; idx < FOUT * QF; idx += 256) {
            int c = idx / QF, k4 = idx % QF;
            *(float4*)&Ws[c * FIN + 4 * (k4 ^ (c & 7))] = W4[idx];
        }
    }
    {
        const float4* X4 = (const float4*)X;
        for (int idx = t; idx < ROWS * QF; idx += 256) {
            int row = idx / QF, q = idx % QF;
            int gr = r0 + row;
            float4 v = make_float4(0.f, 0.f, 0.f, 0.f);
            if (gr < n) v = X4[gr * QF + q];
            *(float4*)&xs[row * FIN + 4 * q] = v;
        }
    }
    __syncthreads();

    int c  = t & 31;
    int rg = t >> 5;

    float acc[RPT][COLS];
#pragma unroll
    for (int i = 0; i < RPT; i++)
#pragma unroll
        for (int j = 0; j < COLS; j++) acc[i][j] = 0.f;

#pragma unroll 2
    for (int k4 = 0; k4 < QF; k4++) {
        int ks = 4 * (k4 ^ (c & 7));
        float4 w0 = *(const float4*)&Ws[c * FIN + ks];
        float4 w1 = (COLS == 2) ? *(const float4*)&Ws[(c + 32) * FIN + ks]
                                : make_float4(0.f, 0.f, 0.f, 0.f);
#pragma unroll
        for (int i = 0; i < RPT; i++) {
            float4 xv = *(const float4*)&xs[(rg + 8 * i) * FIN + 4 * k4];
            acc[i][0] = fmaf(xv.x, w0.x, acc[i][0]);
            acc[i][0] = fmaf(xv.y, w0.y, acc[i][0]);
            acc[i][0] = fmaf(xv.z, w0.z, acc[i][0]);
            acc[i][0] = fmaf(xv.w, w0.w, acc[i][0]);
            if (COLS == 2) {
                acc[i][1] = fmaf(xv.x, w1.x, acc[i][1]);
                acc[i][1] = fmaf(xv.y, w1.y, acc[i][1]);
                acc[i][1] = fmaf(xv.z, w1.z, acc[i][1]);
                acc[i][1] = fmaf(xv.w, w1.w, acc[i][1]);
            }
        }
    }

#pragma unroll
    for (int i = 0; i < RPT; i++) {
        int row = rg + 8 * i;
        int gr  = r0 + row;
        float v0 = acc[i][0];
        float v1 = (COLS == 2) ? acc[i][1] : 0.f;
        if (BIAS) {
            v0 += bias[c];
            if (COLS == 2) v1 += bias[c + 32];
        }
        if (gr < n) {
            if (DSTSEL == 0) {
                g_hfeat[gr * FOUT + c] = v0;
                if (COLS == 2) g_hfeat[gr * FOUT + 32 + c] = v1;
            } else {
                g_hlin16[gr * FOUT + c] = __float2half(v0);
                if (COLS == 2) g_hlin16[gr * FOUT + 32 + c] = __float2half(v1);
            }
        }
        if (COMPE) {
            float ps = v0 * a_s[c];
            float pd = v0 * a_d[c];
            if (COLS == 2) {
                ps += v1 * a_s[c + 32];
                pd += v1 * a_d[c + 32];
            }
            ps = gat_warp_sum(ps);
            pd = gat_warp_sum(pd);
            if (c == 0 && gr < n) {
                g_esrc[gr] = ps;
                g_edst[gr] = pd;
            }
        }
    }
}

// ---------------- warp-per-node softmax aggregation (FOUT=64, fp16 gather) --
// Pass 1a: e_j -> g_ew, warp max m. Pass 1b: w_j = exp(e_j-m) once per edge,
// pre-reduced denominator. Pass 2: half2 gathers (128B/warp/edge).
// OUTSEL: 0 = g_hfeat, 1 = param out.
template <bool RELU, int OUTSEL>
__global__ void gat_agg64_kernel(const float* __restrict__ bias,
                                 float* __restrict__ outparam,
                                 int n) {
    float* out = (OUTSEL == 0) ? g_hfeat : outparam;

    int warp = (blockIdx.x * blockDim.x + threadIdx.x) >> 5;
    int lane = threadIdx.x & 31;
    if (warp >= n) return;

    int beg = g_off[warp];
    int deg = g_off[warp + 1] - beg;
    float ed = g_edst[warp];

    // pass 1a: scores + warp max
    float lm = -FLT_MAX;
    for (int jj = lane; jj < deg; jj += 32) {
        int j  = beg + jj;
        int sv = g_srcs[j];
        float e = g_esrc[sv] + ed;
        e = (e > 0.f) ? e : 0.2f * e;
        g_ew[j] = e;
        lm = fmaxf(lm, e);
    }
    float m = gat_warp_max(lm);

    // pass 1b: exp once per edge + pre-reduced denominator
    float ls = 0.f;
    for (int jj = lane; jj < deg; jj += 32) {
        int j = beg + jj;
        float wv = __expf(g_ew[j] - m);
        g_ew[j] = wv;
        ls += wv;
    }
    float s = gat_warp_sum(ls);
    __threadfence_block();   // g_ew weights visible to all lanes

    // pass 2: half2 gathers, 2 FFMA/edge/lane, 128B per warp per edge
    const __half2* h2 = (const __half2*)g_hlin16;
    float ax = 0.f, ay = 0.f;
#pragma unroll 8
    for (int jj = 0; jj < deg; jj++) {
        int   j  = beg + jj;
        int   sv = g_srcs[j];                 // broadcast
        float wv = g_ew[j];                   // broadcast
        float2 hv = __half22float2(h2[sv * 32 + lane]);
        ax = fmaf(wv, hv.x, ax);
        ay = fmaf(wv, hv.y, ay);
    }

    float inv = 1.f / s;                      // self-loop guarantees s > 0
    float2 bv = ((const float2*)bias)[lane];
    float rx = ax * inv + bv.x;
    float ry = ay * inv + bv.y;
    if (RELU) { rx = fmaxf(rx, 0.f); ry = fmaxf(ry, 0.f); }
    ((float2*)out)[warp * 32 + lane] = make_float2(rx, ry);
}

// ---------------- final agg (FOUT=32) + bias + L2 normalize -> out ----------
__global__ void gat_agg_final_kernel(const float* __restrict__ bias,
                                     float* __restrict__ out,
                                     int n) {
    int warp = (blockIdx.x * blockDim.x + threadIdx.x) >> 5;
    int lane = threadIdx.x & 31;
    if (warp >= n) return;

    int beg = g_off[warp];
    int deg = g_off[warp + 1] - beg;
    float ed = g_edst[warp];

    float lm = -FLT_MAX;
    for (int jj = lane; jj < deg; jj += 32) {
        int j  = beg + jj;
        int sv = g_srcs[j];
        float e = g_esrc[sv] + ed;
        e = (e > 0.f) ? e : 0.2f * e;
        g_ew[j] = e;
        lm = fmaxf(lm, e);
    }
    float m = gat_warp_max(lm);

    float ls = 0.f;
    for (int jj = lane; jj < deg; jj += 32) {
        int j = beg + jj;
        float wv = __expf(g_ew[j] - m);
        g_ew[j] = wv;
        ls += wv;
    }
    float s = gat_warp_sum(ls);
    __threadfence_block();

    const __half* h16 = g_hlin16;   // layer-3 hlin, stride 32
    float a0 = 0.f;
#pragma unroll 8
    for (int jj = 0; jj < deg; jj++) {
        int   j  = beg + jj;
        int   sv = g_srcs[j];
        float wv = g_ew[j];
        a0 = fmaf(wv, __half2float(h16[sv * 32 + lane]), a0);
    }

    float r0 = a0 / s + bias[lane];
    float ss  = gat_warp_sum(r0 * r0);
    float nrm = fmaxf(sqrtf(ss), 1e-12f);
    out[warp * 32 + lane] = r0 / nrm;
}

// ---------------- launch ----------------------------------------------------
extern "C" void kernel_launch(void* const* d_in, const int* in_sizes, int n_in,
                              void* d_out, int out_size) {
    const float* x    = (const float*)d_in[0];
    const int*   ei   = (const int*)d_in[1];     // int32 [2, E]
    const float* Wpre = (const float*)d_in[2];
    const float* bpre = (const float*)d_in[3];
    const float* W1   = (const float*)d_in[4];
    const float* a1s  = (const float*)d_in[5];
    const float* a1d  = (const float*)d_in[6];
    const float* b1   = (const float*)d_in[7];
    const float* W2   = (const float*)d_in[8];
    const float* a2s  = (const float*)d_in[9];
    const float* a2d  = (const float*)d_in[10];
    const float* b2   = (const float*)d_in[11];
    const float* W3   = (const float*)d_in[12];
    const float* a3s  = (const float*)d_in[13];
    const float* a3d  = (const float*)d_in[14];
    const float* b3   = (const float*)d_in[15];
    float*       out  = (float*)d_out;

    int N = in_sizes[0] / 128;
    int E = in_sizes[1] / 2;
    int ET = E + N;

    // ---- edge sort by dst (counting sort) ----
    gat_zero_kernel<<<(N + 255) / 256, 256>>>(N);
    gat_hist_kernel<<<(ET + 255) / 256, 256>>>(ei, E, N);
    gat_scan_kernel<<<1, 1024>>>(N);
    gat_scatter_kernel<<<(ET + 255) / 256, 256>>>(ei, E, N);

    int agg_grid = (N + 7) / 8;   // 8 warps / block

    // ---- linear_pre: hfeat = x @ Wpre^T + bpre (fp32 out) ----
    gat_gemm_kernel<128, 64, 32, true, false, 0, 0><<<(N + 31) / 32, 256>>>(
        x, Wpre, bpre, nullptr, nullptr, N);

    // ---- GAT layer 1 (relu): hlin16 = hfeat @ W1^T, agg -> hfeat ----
    gat_gemm_kernel<64, 64, 64, false, true, 1, 1><<<(N + 63) / 64, 256>>>(
        nullptr, W1, nullptr, a1s, a1d, N);
    gat_agg64_kernel<true, 0><<<agg_grid, 256>>>(b1, nullptr, N);

    // ---- GAT layer 2 (relu) ----
    gat_gemm_kernel<64, 64, 64, false, true, 1, 1><<<(N + 63) / 64, 256>>>(
        nullptr, W2, nullptr, a2s, a2d, N);
    gat_agg64_kernel<true, 0><<<agg_grid, 256>>>(b2, nullptr, N);

    // ---- GAT layer 3 (+ fused row L2-normalize) -> d_out ----
    gat_gemm_kernel<64, 32, 64, false, true, 1, 1><<<(N + 63) / 64, 256>>>(
        nullptr, W3, nullptr, a3s, a3d, N);
    gat_agg_final_kernel<<<agg_grid, 256>>>(b3, out, N);
}

// round 10
// speedup vs baseline: 1.0638x; 1.0638x over previous
#include <cuda_runtime.h>
#include <cuda_bf16.h>
#include <float.h>

// Problem-size upper bounds (from reference setup_inputs)
#define MAXN 50000
#define MAXE 800000
#define MAXET (MAXE + MAXN)   // + self loops

// ---------------- device scratch --------------------------------------------
__device__ float g_hfeat[MAXN * 64];
__device__ float g_hlin [MAXN * 64];
__device__ float g_esrc [MAXN];
__device__ float g_edst [MAXN];
__device__ float g_ew   [MAXET];
__device__ int   g_hist [MAXN];
__device__ int   g_off  [MAXN + 1];
__device__ int   g_cursor[MAXN];
__device__ int   g_srcs [MAXET];

// ---------------- helpers ---------------------------------------------------
__device__ __forceinline__ float gat_warp_sum(float v) {
#pragma unroll
    for (int o = 16; o; o >>= 1) v += __shfl_xor_sync(0xffffffffu, v, o);
    return v;
}
__device__ __forceinline__ float gat_warp_max(float v) {
#pragma unroll
    for (int o = 16; o; o >>= 1) v = fmaxf(v, __shfl_xor_sync(0xffffffffu, v, o));
    return v;
}

// ---------------- edge sorting (counting sort by dst) -----------------------
__global__ void gat_zero_kernel(int n) {
    int i = blockIdx.x * blockDim.x + threadIdx.x;
    if (i < n) g_hist[i] = 0;
}

// edge_index is int32 [2, E] row-major: ei[i] = src, ei[E+i] = dst.
__global__ void gat_hist_kernel(const int* __restrict__ ei, int E, int n) {
    int i = blockIdx.x * blockDim.x + threadIdx.x;
    int total = E + n;
    if (i >= total) return;
    int d = (i < E) ? ei[E + i] : (i - E);
    if ((unsigned)d >= (unsigned)n) return;
    atomicAdd(&g_hist[d], 1);
}

__global__ void gat_scan_kernel(int n) {
    __shared__ int partial[1024];
    int t = threadIdx.x;
    int chunk = (n + 1023) / 1024;
    int begin = t * chunk;
    int endi  = min(begin + chunk, n);
    int sum = 0;
    for (int i = begin; i < endi; i++) sum += g_hist[i];
    partial[t] = sum;
    __syncthreads();
#pragma unroll
    for (int d = 1; d < 1024; d <<= 1) {
        int v = (t >= d) ? partial[t - d] : 0;
        __syncthreads();
        partial[t] += v;
        __syncthreads();
    }
    int run = (t == 0) ? 0 : partial[t - 1];
    for (int i = begin; i < endi; i++) {
        g_off[i]    = run;
        g_cursor[i] = run;
        run += g_hist[i];
    }
    if (t == 0) g_off[n] = partial[1023];
}

__global__ void gat_scatter_kernel(const int* __restrict__ ei, int E, int n) {
    int i = blockIdx.x * blockDim.x + threadIdx.x;
    int total = E + n;
    if (i >= total) return;
    int s, d;
    if (i < E) { s = ei[i]; d = ei[E + i]; }
    else       { s = d = i - E; }
    if ((unsigned)d >= (unsigned)n || (unsigned)s >= (unsigned)n) return;
    int pos = atomicAdd(&g_cursor[d], 1);
    g_srcs[pos] = s;
}

// ---------------- tiled GEMM: out = X @ W^T (+bias), optional e_src/e_dst ---
// Block = 256 threads, tile = ROWS x FOUT. W stored c-major with float4 XOR
// swizzle: (c, k4) at Ws[c*FIN + 4*(k4 ^ (c&7))] -> conflict-free both ways.
// SRCSEL: 0 = param X, 1 = g_hfeat.   DSTSEL: 0 = g_hfeat, 1 = g_hlin.
template <int FIN, int FOUT, int ROWS, bool BIAS, bool COMPE, int SRCSEL, int DSTSEL>
__global__ void gat_gemm_kernel(const float* __restrict__ Xparam,
                                const float* __restrict__ W,
                                const float* __restrict__ bias,
                                const float* __restrict__ a_s,
                                const float* __restrict__ a_d,
                                int n) {
    const float* X   = (SRCSEL == 0) ? Xparam : g_hfeat;
    float*       out = (DSTSEL == 0) ? g_hfeat : g_hlin;

    constexpr int COLS = FOUT / 32;
    constexpr int RPT  = ROWS / 8;
    constexpr int QF   = FIN / 4;

    __shared__ float xs[ROWS * FIN];
    __shared__ float Ws[FOUT * FIN];

    int t  = threadIdx.x;
    int r0 = blockIdx.x * ROWS;

    {
        const float4* W4 = (const float4*)W;
        for (int idx = t; idx < FOUT * QF; idx += 256) {
            int c = idx / QF, k4 = idx % QF;
            *(float4*)&Ws[c * FIN + 4 * (k4 ^ (c & 7))] = W4[idx];
        }
    }
    {
        const float4* X4 = (const float4*)X;
        for (int idx = t; idx < ROWS * QF; idx += 256) {
            int row = idx / QF, q = idx % QF;
            int gr = r0 + row;
            float4 v = make_float4(0.f, 0.f, 0.f, 0.f);
            if (gr < n) v = X4[gr * QF + q];
            *(float4*)&xs[row * FIN + 4 * q] = v;
        }
    }
    __syncthreads();

    int c  = t & 31;
    int rg = t >> 5;

    float acc[RPT][COLS];
#pragma unroll
    for (int i = 0; i < RPT; i++)
#pragma unroll
        for (int j = 0; j < COLS; j++) acc[i][j] = 0.f;

#pragma unroll 2
    for (int k4 = 0; k4 < QF; k4++) {
        int ks = 4 * (k4 ^ (c & 7));
        float4 w0 = *(const float4*)&Ws[c * FIN + ks];
        float4 w1 = (COLS == 2) ? *(const float4*)&Ws[(c + 32) * FIN + ks]
                                : make_float4(0.f, 0.f, 0.f, 0.f);
#pragma unroll
        for (int i = 0; i < RPT; i++) {
            float4 xv = *(const float4*)&xs[(rg + 8 * i) * FIN + 4 * k4];
            acc[i][0] = fmaf(xv.x, w0.x, acc[i][0]);
            acc[i][0] = fmaf(xv.y, w0.y, acc[i][0]);
            acc[i][0] = fmaf(xv.z, w0.z, acc[i][0]);
            acc[i][0] = fmaf(xv.w, w0.w, acc[i][0]);
            if (COLS == 2) {
                acc[i][1] = fmaf(xv.x, w1.x, acc[i][1]);
                acc[i][1] = fmaf(xv.y, w1.y, acc[i][1]);
                acc[i][1] = fmaf(xv.z, w1.z, acc[i][1]);
                acc[i][1] = fmaf(xv.w, w1.w, acc[i][1]);
            }
        }
    }

#pragma unroll
    for (int i = 0; i < RPT; i++) {
        int row = rg + 8 * i;
        int gr  = r0 + row;
        float v0 = acc[i][0];
        float v1 = (COLS == 2) ? acc[i][1] : 0.f;
        if (BIAS) {
            v0 += bias[c];
            if (COLS == 2) v1 += bias[c + 32];
        }
        if (gr < n) {
            out[gr * FOUT + c] = v0;
            if (COLS == 2) out[gr * FOUT + 32 + c] = v1;
        }
        if (COMPE) {
            float ps = v0 * a_s[c];
            float pd = v0 * a_d[c];
            if (COLS == 2) {
                ps += v1 * a_s[c + 32];
                pd += v1 * a_d[c + 32];
            }
            ps = gat_warp_sum(ps);
            pd = gat_warp_sum(pd);
            if (c == 0 && gr < n) {
                g_esrc[gr] = ps;
                g_edst[gr] = pd;
            }
        }
    }
}

// ---------------- warp-per-node softmax aggregation (FOUT=64) ---------------
// Fast path (deg <= 32, ~99.96% of nodes): the entire edge list lives in one
// register per lane. No g_ew traffic, no fence; pass 2 broadcasts sv/w via
// shfl (ALU) leaving ONE coalesced gather as the only memory op per edge.
// Fallback (deg > 32): R8-style g_ew two-pass.
// OUTSEL: 0 = g_hfeat, 1 = param out.
template <bool RELU, int OUTSEL>
__global__ void gat_agg64_kernel(const float* __restrict__ bias,
                                 float* __restrict__ outparam,
                                 int n) {
    const float2* h2 = (const float2*)g_hlin;
    float* out = (OUTSEL == 0) ? g_hfeat : outparam;

    int warp = (blockIdx.x * blockDim.x + threadIdx.x) >> 5;
    int lane = threadIdx.x & 31;
    if (warp >= n) return;

    int beg = g_off[warp];
    int deg = g_off[warp + 1] - beg;
    float ed = g_edst[warp];

    float ax = 0.f, ay = 0.f, s;

    if (deg <= 32) {
        // ---- register-resident fast path ----
        int   sv_r = 0;
        float e    = -FLT_MAX;
        if (lane < deg) {
            sv_r = g_srcs[beg + lane];
            e = g_esrc[sv_r] + ed;
            e = (e > 0.f) ? e : 0.2f * e;
        }
        float m   = gat_warp_max(e);
        float w_r = (lane < deg) ? __expf(e - m) : 0.f;
        s = gat_warp_sum(w_r);

#pragma unroll 8
        for (int jj = 0; jj < deg; jj++) {
            int   sv = __shfl_sync(0xffffffffu, sv_r, jj);
            float wv = __shfl_sync(0xffffffffu, w_r, jj);
            float2 hv = h2[sv * 32 + lane];
            ax = fmaf(wv, hv.x, ax);
            ay = fmaf(wv, hv.y, ay);
        }
    } else {
        // ---- general path via g_ew ----
        float lm = -FLT_MAX;
        for (int jj = lane; jj < deg; jj += 32) {
            int j  = beg + jj;
            int sv = g_srcs[j];
            float e = g_esrc[sv] + ed;
            e = (e > 0.f) ? e : 0.2f * e;
            g_ew[j] = e;
            lm = fmaxf(lm, e);
        }
        float m = gat_warp_max(lm);

        float ls = 0.f;
        for (int jj = lane; jj < deg; jj += 32) {
            int j = beg + jj;
            float wv = __expf(g_ew[j] - m);
            g_ew[j] = wv;
            ls += wv;
        }
        s = gat_warp_sum(ls);
        __threadfence_block();

#pragma unroll 4
        for (int jj = 0; jj < deg; jj++) {
            int   j  = beg + jj;
            int   sv = g_srcs[j];
            float wv = g_ew[j];
            float2 hv = h2[sv * 32 + lane];
            ax = fmaf(wv, hv.x, ax);
            ay = fmaf(wv, hv.y, ay);
        }
    }

    float inv = 1.f / s;                      // self-loop guarantees s > 0
    float2 bv = ((const float2*)bias)[lane];
    float rx = ax * inv + bv.x;
    float ry = ay * inv + bv.y;
    if (RELU) { rx = fmaxf(rx, 0.f); ry = fmaxf(ry, 0.f); }
    ((float2*)out)[warp * 32 + lane] = make_float2(rx, ry);
}

// ---------------- final agg (FOUT=32) + bias + L2 normalize -> out ----------
__global__ void gat_agg_final_kernel(const float* __restrict__ bias,
                                     float* __restrict__ out,
                                     int n) {
    const float* hlin = g_hlin;   // layer-3 hlin, stride 32

    int warp = (blockIdx.x * blockDim.x + threadIdx.x) >> 5;
    int lane = threadIdx.x & 31;
    if (warp >= n) return;

    int beg = g_off[warp];
    int deg = g_off[warp + 1] - beg;
    float ed = g_edst[warp];

    float a0 = 0.f, s;

    if (deg <= 32) {
        int   sv_r = 0;
        float e    = -FLT_MAX;
        if (lane < deg) {
            sv_r = g_srcs[beg + lane];
            e = g_esrc[sv_r] + ed;
            e = (e > 0.f) ? e : 0.2f * e;
        }
        float m   = gat_warp_max(e);
        float w_r = (lane < deg) ? __expf(e - m) : 0.f;
        s = gat_warp_sum(w_r);

#pragma unroll 8
        for (int jj = 0; jj < deg; jj++) {
            int   sv = __shfl_sync(0xffffffffu, sv_r, jj);
            float wv = __shfl_sync(0xffffffffu, w_r, jj);
            a0 = fmaf(wv, hlin[sv * 32 + lane], a0);
        }
    } else {
        float lm = -FLT_MAX;
        for (int jj = lane; jj < deg; jj += 32) {
            int j  = beg + jj;
            int sv = g_srcs[j];
            float e = g_esrc[sv] + ed;
            e = (e > 0.f) ? e : 0.2f * e;
            g_ew[j] = e;
            lm = fmaxf(lm, e);
        }
        float m = gat_warp_max(lm);

        float ls = 0.f;
        for (int jj = lane; jj < deg; jj += 32) {
            int j = beg + jj;
            float wv = __expf(g_ew[j] - m);
            g_ew[j] = wv;
            ls += wv;
        }
        s = gat_warp_sum(ls);
        __threadfence_block();

#pragma unroll 4
        for (int jj = 0; jj < deg; jj++) {
            int   j  = beg + jj;
            int   sv = g_srcs[j];
            float wv = g_ew[j];
            a0 = fmaf(wv, hlin[sv * 32 + lane], a0);
        }
    }

    float r0 = a0 / s + bias[lane];
    float ss  = gat_warp_sum(r0 * r0);
    float nrm = fmaxf(sqrtf(ss), 1e-12f);
    out[warp * 32 + lane] = r0 / nrm;
}

// ---------------- launch ----------------------------------------------------
extern "C" void kernel_launch(void* const* d_in, const int* in_sizes, int n_in,
                              void* d_out, int out_size) {
    const float* x    = (const float*)d_in[0];
    const int*   ei   = (const int*)d_in[1];     // int32 [2, E]
    const float* Wpre = (const float*)d_in[2];
    const float* bpre = (const float*)d_in[3];
    const float* W1   = (const float*)d_in[4];
    const float* a1s  = (const float*)d_in[5];
    const float* a1d  = (const float*)d_in[6];
    const float* b1   = (const float*)d_in[7];
    const float* W2   = (const float*)d_in[8];
    const float* a2s  = (const float*)d_in[9];
    const float* a2d  = (const float*)d_in[10];
    const float* b2   = (const float*)d_in[11];
    const float* W3   = (const float*)d_in[12];
    const float* a3s  = (const float*)d_in[13];
    const float* a3d  = (const float*)d_in[14];
    const float* b3   = (const float*)d_in[15];
    float*       out  = (float*)d_out;

    int N = in_sizes[0] / 128;
    int E = in_sizes[1] / 2;
    int ET = E + N;

    // ---- edge sort by dst (counting sort) ----
    gat_zero_kernel<<<(N + 255) / 256, 256>>>(N);
    gat_hist_kernel<<<(ET + 255) / 256, 256>>>(ei, E, N);
    gat_scan_kernel<<<1, 1024>>>(N);
    gat_scatter_kernel<<<(ET + 255) / 256, 256>>>(ei, E, N);

    int agg_grid = (N + 7) / 8;   // 8 warps / block

    // ---- linear_pre: hfeat = x @ Wpre^T + bpre (ROWS=32: 48KB smem cap) ----
    gat_gemm_kernel<128, 64, 32, true, false, 0, 0><<<(N + 31) / 32, 256>>>(
        x, Wpre, bpre, nullptr, nullptr, N);

    // ---- GAT layer 1 (relu): hlin = hfeat @ W1^T, agg -> hfeat ----
    gat_gemm_kernel<64, 64, 64, false, true, 1, 1><<<(N + 63) / 64, 256>>>(
        nullptr, W1, nullptr, a1s, a1d, N);
    gat_agg64_kernel<true, 0><<<agg_grid, 256>>>(b1, nullptr, N);

    // ---- GAT layer 2 (relu) ----
    gat_gemm_kernel<64, 64, 64, false, true, 1, 1><<<(N + 63) / 64, 256>>>(
        nullptr, W2, nullptr, a2s, a2d, N);
    gat_agg64_kernel<true, 0><<<agg_grid, 256>>>(b2, nullptr, N);

    // ---- GAT layer 3 (+ fused row L2-normalize) -> d_out ----
    gat_gemm_kernel<64, 32, 64, false, true, 1, 1><<<(N + 63) / 64, 256>>>(
        nullptr, W3, nullptr, a3s, a3d, N);
    gat_agg_final_kernel<<<agg_grid, 256>>>(b3, out, N);
}